// round 10
// baseline (speedup 1.0000x reference)
#include <cuda_runtime.h>
#include <cstdint>
#include <cstddef>

#define T_STEPS 2048
#define BATCH   512
#define HID     33
#define G4      132
#define ODIM    18
#define H1DIM   72
#define CS      128
#define NCHUNK  (T_STEPS / CS)      // 16
#define NWAVE   (NCHUNK + 2)        // 18

// Static device scratch (allocation-free).
__device__ float g_y0[(size_t)T_STEPS * BATCH * HID];
__device__ float g_y1[(size_t)T_STEPS * BATCH * HID];
__device__ float g_h[3][BATCH][HID];
__device__ float g_c[3][BATCH][HID];

typedef unsigned long long u64;

__device__ __forceinline__ void fma2(u64 &acc, u64 a, u64 b) {
    asm("fma.rn.f32x2 %0, %1, %2, %0;" : "+l"(acc) : "l"(a), "l"(b));
}
__device__ __forceinline__ u64 pack2(float lo, float hi) {
    u64 r; asm("mov.b64 %0, {%1,%2};" : "=l"(r) : "f"(lo), "f"(hi)); return r;
}
__device__ __forceinline__ float2 unpack2(u64 v) {
    float2 r; asm("mov.b64 {%0,%1}, %2;" : "=f"(r.x), "=f"(r.y) : "l"(v)); return r;
}
__device__ __forceinline__ float sigm_(float x) {
    return __fdividef(1.f, 1.f + __expf(-x));
}
__device__ __forceinline__ float tanh_(float x) {
    float e = __expf(2.f * x);
    return 1.f - __fdividef(2.f, e + 1.f);
}

// ---------------------------------------------------------------------------
// One chunk of one layer for one batch element. 132 threads = 33 groups of 4.
// Thread (p,q): partial dots of unit p's 4 gates over k-quarter q of z=[h|x].
// z logical k: [0..33)=h, [40..40+IN)=x, rest 0. Quarter q = k in [20q,20q+20),
// stored at z_sh[par][q][0..19] (stride 24 floats -> conflict-free banks).
// XOR-layout accumulators: acc[i] = partial of gate-slot (q^i) of unit p.
// 3-shuffle butterfly reduce + 2-shuffle in-warp cell update; ONE barrier/step.
// ---------------------------------------------------------------------------
template<int IN, bool XBF, bool YW>
__device__ __forceinline__ void run_chunk(
    int b, int chunk,
    const float* __restrict__ xp,
    const float* __restrict__ Wih, const float* __restrict__ Whh,
    const float* __restrict__ bih, const float* __restrict__ bhh,
    float* __restrict__ yp, float* __restrict__ hrow, float* __restrict__ crow,
    float* __restrict__ hid,
    float (*z_sh)[4][24])
{
    const int tid = threadIdx.x;
    const int p   = tid >> 2;        // unit 0..32
    const int q   = tid & 3;         // quarter & gate-slot (0=i,1=f,2=g,3=o)
    const int t0  = chunk * CS;
    const unsigned mask = (tid < 128) ? 0xFFFFFFFFu : 0xFu;

    // weight element for gate row G at logical k
    auto wk = [&](int G, int k) -> float {
        if (k < HID)               return Whh[G * HID + k];
        if (k < 40)                return 0.f;
        if (k - 40 < IN)           return Wih[G * IN + (k - 40)];
        return 0.f;
    };

    // w[i][j]: weights of gate-slot (q^i), this thread's k-quarter, pair j
    u64 w[4][10];
#pragma unroll
    for (int i = 0; i < 4; i++) {
        const int G = (q ^ i) * HID + p;
#pragma unroll
        for (int j = 0; j < 10; j++) {
            int k0 = 20 * q + 2 * j;
            w[i][j] = pack2(wk(G, k0), wk(G, k0 + 1));
        }
    }
    const int   Gown = q * HID + p;
    const float bias = bih[Gown] + bhh[Gown];
    // slot 2 (g) uses tanh(x) = 2*sigm(2x) - 1; others sigm
    const float S = (q == 2) ? 2.f : 1.f;
    const float A = (q == 2) ? 2.f : 1.f;
    const float Bc = (q == 2) ? -1.f : 0.f;

    auto xval = [&](int t, int i) -> float {
        if (XBF) return xp[((size_t)b * T_STEPS + t) * IN + i];
        else     return xp[((size_t)t * BATCH + b) * HID + i];
    };

    const int zq = p / 20, zi = p % 20;   // h slot of unit p
    // (x_i goes to quarter 2 + i/20, idx i%20)

    // ---- init: zero both parities (pads stay 0), then seed h/c/x ----
    for (int i = tid; i < 2 * 4 * 24; i += G4) (&z_sh[0][0][0])[i] = 0.f;
    __syncthreads();
    float c = 0.f;
    if (chunk > 0 && q == 1) { c = crow[p]; z_sh[0][zq][zi] = hrow[p]; }
    if (q == 3 && p < IN)    z_sh[0][2 + zq][zi] = xval(t0, p);
    __syncthreads();

    float xr = (q == 3 && p < IN) ? xval(t0 + 1, p) : 0.f;
    float hval = 0.f;

    for (int s = 0; s < CS; ++s) {
        const int t  = t0 + s;
        const int pc = s & 1, pn = pc ^ 1;

        // depth-2 x prefetch, clamped to this chunk (producer fence = launch order)
        float xr2 = 0.f;
        if (q == 3 && p < IN && (s + 2) < CS) xr2 = xval(t + 2, p);

        // 4 gate-slot partial dots over this thread's 5 operand vectors
        u64 a0 = 0ull, a1 = 0ull, a2 = 0ull, a3 = 0ull;
        const ulonglong2* zv = (const ulonglong2*)z_sh[pc][q];
#pragma unroll
        for (int v = 0; v < 5; v++) {
            ulonglong2 d = zv[v];
            fma2(a0, w[0][2 * v], d.x); fma2(a0, w[0][2 * v + 1], d.y);
            fma2(a1, w[1][2 * v], d.x); fma2(a1, w[1][2 * v + 1], d.y);
            fma2(a2, w[2][2 * v], d.x); fma2(a2, w[2][2 * v + 1], d.y);
            fma2(a3, w[3][2 * v], d.x); fma2(a3, w[3][2 * v + 1], d.y);
        }
        float2 e0 = unpack2(a0), e1 = unpack2(a1), e2 = unpack2(a2), e3 = unpack2(a3);
        float p0 = e0.x + e0.y;   // partial of slot q   (own)
        float p1 = e1.x + e1.y;   // partial of slot q^1
        float p2 = e2.x + e2.y;   // partial of slot q^2
        float p3 = e3.x + e3.y;   // partial of slot q^3

        // butterfly reduce: a = full presum of own gate-slot q
        float a  = p0 + __shfl_xor_sync(mask, p1, 1);
        float bb = p2 + __shfl_xor_sync(mask, p3, 1);
        a += __shfl_xor_sync(mask, bb, 2);

        // activation of own gate
        float v  = A * sigm_(S * (a + bias)) + Bc;
        // in-warp cell update: lane q^2 partner
        float wv = __shfl_xor_sync(mask, v, 2);     // q0<->g, q1<->o, q2<->i, q3<->f
        float u  = v * wv;                          // q0: i*g (q2: g*i)
        float ur = __shfl_xor_sync(mask, u, 1);     // q1 receives i*g from q0
        c    = fmaf(v, c, ur);                      // valid at q==1: f*c + i*g
        hval = wv * tanh_(c);                       // valid at q==1: o*tanh(c)

        if (q == 1) {
            z_sh[pn][zq][zi] = hval;
            if (YW) yp[((size_t)t * BATCH + b) * HID + p] = hval;
            if (t == T_STEPS - 1) hid[b * HID + p] = hval;
        } else if (q == 3 && p < IN) {
            z_sh[pn][2 + zq][zi] = xr;              // publish x(t+1)
            xr = xr2;
        }
        __syncthreads();
    }

    if (q == 1) { hrow[p] = hval; crow[p] = c; }
}

// ---------------------------------------------------------------------------
// Pipeline wave: CTA (b, layer) runs chunk = wave - layer.
// ---------------------------------------------------------------------------
__global__ __launch_bounds__(G4)
void wave_kernel(int wave, const float* __restrict__ x,
                 const float* __restrict__ Wih0, const float* __restrict__ Whh0,
                 const float* __restrict__ bih0, const float* __restrict__ bhh0,
                 const float* __restrict__ Wih1, const float* __restrict__ Whh1,
                 const float* __restrict__ bih1, const float* __restrict__ bhh1,
                 const float* __restrict__ Wih2, const float* __restrict__ Whh2,
                 const float* __restrict__ bih2, const float* __restrict__ bhh2,
                 float* __restrict__ hid)
{
    const int b     = blockIdx.x;
    const int layer = blockIdx.y;
    const int chunk = wave - layer;
    if (chunk < 0 || chunk >= NCHUNK) return;

    __shared__ __align__(16) float z_sh[2][4][24];

    if (layer == 0)
        run_chunk<11, true,  true >(b, chunk, x,    Wih0, Whh0, bih0, bhh0,
                                    g_y0, g_h[0][b], g_c[0][b],
                                    hid,                   z_sh);
    else if (layer == 1)
        run_chunk<33, false, true >(b, chunk, g_y0, Wih1, Whh1, bih1, bhh1,
                                    g_y1, g_h[1][b], g_c[1][b],
                                    hid + BATCH * HID,     z_sh);
    else
        run_chunk<33, false, false>(b, chunk, g_y1, Wih2, Whh2, bih2, bhh2,
                                    nullptr, g_h[2][b], g_c[2][b],
                                    hid + 2 * BATCH * HID, z_sh);
}

// ---------------------------------------------------------------------------
// MLP head: out = GELU(hid@W1^T + b1) @ W2^T + b2
// ---------------------------------------------------------------------------
__global__ __launch_bounds__(H1DIM)
void head_kernel(const float* __restrict__ hid,
                 const float* __restrict__ W1, const float* __restrict__ b1,
                 const float* __restrict__ W2, const float* __restrict__ b2,
                 float* __restrict__ out)
{
    const int rr = blockIdx.x;
    const int u  = threadIdx.x;
    __shared__ float hrow[HID];
    __shared__ float h1[H1DIM];

    if (u < HID) hrow[u] = hid[rr * HID + u];
    __syncthreads();

    float s = b1[u];
#pragma unroll
    for (int m = 0; m < HID; m++) s += W1[u * HID + m] * hrow[m];
    h1[u] = 0.5f * s * (1.f + erff(s * 0.70710678118654752f));  // exact GELU
    __syncthreads();

    if (u < ODIM) {
        float s2 = b2[u];
#pragma unroll
        for (int m = 0; m < H1DIM; m++) s2 += W2[u * H1DIM + m] * h1[m];
        out[rr * ODIM + u] = s2;
    }
}

extern "C" void kernel_launch(void* const* d_in, const int* in_sizes, int n_in,
                              void* d_out, int out_size)
{
    const float* x    = (const float*)d_in[0];
    const float* Wih0 = (const float*)d_in[1];
    const float* Whh0 = (const float*)d_in[2];
    const float* bih0 = (const float*)d_in[3];
    const float* bhh0 = (const float*)d_in[4];
    const float* Wih1 = (const float*)d_in[5];
    const float* Whh1 = (const float*)d_in[6];
    const float* bih1 = (const float*)d_in[7];
    const float* bhh1 = (const float*)d_in[8];
    const float* Wih2 = (const float*)d_in[9];
    const float* Whh2 = (const float*)d_in[10];
    const float* bih2 = (const float*)d_in[11];
    const float* bhh2 = (const float*)d_in[12];
    const float* W1   = (const float*)d_in[13];
    const float* b1   = (const float*)d_in[14];
    const float* W2   = (const float*)d_in[15];
    const float* b2   = (const float*)d_in[16];

    float* out = (float*)d_out;                      // [3, 512, 18]
    float* hid = out + 3 * BATCH * ODIM;             // [3, 512, 33]

    dim3 wgrid(BATCH, 3);
    for (int w = 0; w < NWAVE; ++w) {
        wave_kernel<<<wgrid, G4>>>(w, x,
                                   Wih0, Whh0, bih0, bhh0,
                                   Wih1, Whh1, bih1, bhh1,
                                   Wih2, Whh2, bih2, bhh2, hid);
    }
    head_kernel<<<3 * BATCH, H1DIM>>>(hid, W1, b1, W2, b2, out);
}